// round 5
// baseline (speedup 1.0000x reference)
#include <cuda_runtime.h>
#include <cstdint>

#define BATCH 256
#define NBANK 32768
#define DIM   2048
#define KSEL  8192

// ---------------- scratch (static device globals; no allocation) ----------------
__device__ float    g_sim[(size_t)BATCH * NBANK];   // 32 MB
__device__ unsigned g_bitmap[BATCH * 1024];         // 1 MB  (32768 bits per row)
__device__ int      g_posidx1[BATCH];               // argmax of g1 (wogan -> mat = f.k)
__device__ int      g_posidx2[BATCH];               // argmax of g2 (-> mat_sim)
__device__ float    g_ce[BATCH];

// ---------------- threefry2x32 (bit-exact JAX) ----------------
__device__ __forceinline__ void tf2x32(unsigned k0, unsigned k1, unsigned x0, unsigned x1,
                                       unsigned &o0, unsigned &o1) {
    unsigned k2 = k0 ^ k1 ^ 0x1BD11BDAu;
    x0 += k0; x1 += k1;
#define TFR(r) { x0 += x1; x1 = (x1 << (r)) | (x1 >> (32 - (r))); x1 ^= x0; }
    TFR(13) TFR(15) TFR(26) TFR(6)
    x0 += k1; x1 += k2 + 1u;
    TFR(17) TFR(29) TFR(16) TFR(24)
    x0 += k2; x1 += k0 + 2u;
    TFR(13) TFR(15) TFR(26) TFR(6)
    x0 += k0; x1 += k1 + 3u;
    TFR(17) TFR(29) TFR(16) TFR(24)
    x0 += k1; x1 += k2 + 4u;
    TFR(13) TFR(15) TFR(26) TFR(6)
    x0 += k2; x1 += k0 + 5u;
#undef TFR
    o0 = x0; o1 = x1;
}

// jax_threefry_partitionable=True, 32-bit random bits at flat counter c:
// counter words (hi,lo) = (0,c); bits = out1 ^ out2.  (Verified against jax prng.py.)
#define RNG_XOR_WORDS 1
__device__ __forceinline__ unsigned rbits32(unsigned k0, unsigned k1, unsigned c) {
    unsigned o0, o1; tf2x32(k0, k1, 0u, c, o0, o1);
#if RNG_XOR_WORDS
    return o0 ^ o1;
#else
    return o0;
#endif
}

// ---------------- kernel 1: copy features -> new_features region ----------------
// dst may be misaligned by p floats (0..3). Peel p scalars so dst+p is 16B-aligned,
// then 4 scalar loads + 1 STG.128 per 16 bytes (src stays scalar: alignment unknown).
__global__ void k_copy_shift(const float* __restrict__ src, float* __restrict__ dst, int p) {
    const size_t n = (size_t)NBANK * DIM;
    const size_t tidg = (size_t)blockIdx.x * blockDim.x + threadIdx.x;
    const size_t stride = (size_t)gridDim.x * blockDim.x;
    if (tidg < (size_t)p) dst[tidg] = src[tidg];          // peel head
    const size_t nv = (n - p) >> 2;                       // # of float4 stores
    float4* __restrict__ dv = (float4*)(dst + p);
    const float* __restrict__ sv = src + p;
    for (size_t i = tidg; i < nv; i += stride) {
        size_t b = i << 2;
        float4 v = make_float4(sv[b], sv[b + 1], sv[b + 2], sv[b + 3]);
        dv[i] = v;
    }
    for (size_t i = p + (nv << 2) + tidg; i < n; i += stride) dst[i] = src[i];  // tail
}

// ---------------- kernel 2: per-row RNG + exact top-K threshold + argmaxes ----------------
// dynamic smem layout (uint32): keys[32768] | hist[2048] | hist2[4096] | bitmap[1024] | gsum[512]
__global__ __launch_bounds__(512) void k_select(const int* __restrict__ labels,
                                                const int* __restrict__ indexes) {
    extern __shared__ unsigned sm[];
    unsigned* keys   = sm;
    unsigned* hist   = keys + NBANK;
    unsigned* hist2  = hist + 2048;
    unsigned* bitmap = hist2 + 4096;
    unsigned* gsum   = bitmap + 1024;

    __shared__ unsigned long long sb1, sb2;
    __shared__ int sBin, sCab, sMneed, eqn;
    __shared__ unsigned sT;
    __shared__ int eqlist[128];

    const int row = blockIdx.x;
    const int tid = threadIdx.x;
    const int nt  = blockDim.x;

    // foldlike split: kg_i = (o0,o1) of threefry((0,42),(0,i))
    unsigned K1a, K1b, K2a, K2b, K3a, K3b;
    tf2x32(0u, 42u, 0u, 0u, K1a, K1b);
    tf2x32(0u, 42u, 0u, 1u, K2a, K2b);
    tf2x32(0u, 42u, 0u, 2u, K3a, K3b);

    const int bl = labels[indexes[row]];

    if (tid == 0) { sb1 = 0ull; sb2 = 0ull; eqn = 0; }
    for (int i = tid; i < 2048 + 4096 + 1024 + 512; i += nt) hist[i] = 0u;
    __syncthreads();

    // pass 1: keys + histogram (negatives) + g1/g2 argmax (positives only)
    unsigned long long b1 = 0ull, b2 = 0ull;
    for (int j = tid; j < NBANK; j += nt) {
        unsigned flat = (unsigned)(row * NBANK + j);
        unsigned kk;
        if (labels[j] == bl) {
            unsigned m1 = rbits32(K1a, K1b, flat) >> 9;
            unsigned m2 = rbits32(K2a, K2b, flat) >> 9;
            unsigned nj = ~(unsigned)j;   // tie-break: larger ~j == smaller j
            unsigned long long s1 = ((unsigned long long)(m1 + 1u) << 32) | nj;
            unsigned long long s2 = ((unsigned long long)(m2 + 1u) << 32) | nj;
            if (s1 > b1) b1 = s1;
            if (s2 > b2) b2 = s2;
            kk = 0xFFFFFFFFu;             // sentinel: positive, excluded from top-K
        } else {
            unsigned m3 = rbits32(K3a, K3b, flat) >> 9;   // 23-bit key, monotone with gumbel
            atomicAdd(&hist[m3 >> 12], 1u);
            kk = m3;
        }
        keys[j] = kk;
    }
    atomicMax(&sb1, b1);
    atomicMax(&sb2, b2);
    __syncthreads();

    // level-1 threshold search over 2048 bins (groups of 8)
    if (tid < 256) {
        unsigned s = 0;
        #pragma unroll
        for (int i = 0; i < 8; i++) s += hist[tid * 8 + i];
        gsum[tid] = s;
    }
    __syncthreads();
    if (tid == 0) {
        unsigned acc = 0; int bin = -1;
        for (int g = 255; g >= 0; --g) {
            if (acc + gsum[g] >= (unsigned)KSEL) {
                for (int bb = g * 8 + 7;; --bb) {
                    if (acc + hist[bb] >= (unsigned)KSEL) { bin = bb; break; }
                    acc += hist[bb];
                }
                break;
            }
            acc += gsum[g];
        }
        sBin = bin; sCab = (int)acc;   // acc = count of keys strictly above bin
    }
    __syncthreads();
    const int bin = sBin;

    // level-2: refine within the threshold bin (low 12 bits)
    for (int j = tid; j < NBANK; j += nt) {
        unsigned kk = keys[j];
        if (kk != 0xFFFFFFFFu && (int)(kk >> 12) == bin) atomicAdd(&hist2[kk & 0xFFF], 1u);
    }
    __syncthreads();
    if (tid < 512) {
        unsigned s = 0;
        #pragma unroll
        for (int i = 0; i < 8; i++) s += hist2[tid * 8 + i];
        gsum[tid] = s;
    }
    __syncthreads();
    if (tid == 0) {
        unsigned acc = (unsigned)sCab; int v = -1;
        for (int g = 511; g >= 0; --g) {
            if (acc + gsum[g] >= (unsigned)KSEL) {
                for (int bb = g * 8 + 7;; --bb) {
                    if (acc + hist2[bb] >= (unsigned)KSEL) { v = bb; break; }
                    acc += hist2[bb];
                }
                break;
            }
            acc += gsum[g];
        }
        sT = ((unsigned)bin << 12) | (unsigned)v;   // exact 23-bit threshold
        sMneed = KSEL - (int)acc;                   // # of ==T elems, lowest index first
    }
    __syncthreads();
    const unsigned T = sT;

    // pass 3: bitmap of strictly-greater; collect ==T candidates
    for (int j = tid; j < NBANK; j += nt) {
        unsigned kk = keys[j];
        if (kk == 0xFFFFFFFFu) continue;
        if (kk > T) {
            atomicOr(&bitmap[j >> 5], 1u << (j & 31));
        } else if (kk == T) {
            int p = atomicAdd(&eqn, 1);
            if (p < 128) eqlist[p] = j;
        }
    }
    __syncthreads();
    if (tid == 0) {
        int n = eqn; if (n > 128) n = 128;
        for (int a = 1; a < n; a++) {              // sort ascending (n is tiny)
            int x = eqlist[a], c = a - 1;
            while (c >= 0 && eqlist[c] > x) { eqlist[c + 1] = eqlist[c]; c--; }
            eqlist[c + 1] = x;
        }
        int m = sMneed; if (m > n) m = n;
        for (int a = 0; a < m; a++) { int j = eqlist[a]; bitmap[j >> 5] |= 1u << (j & 31); }
        g_posidx1[row] = (int)(~(unsigned)(sb1 & 0xFFFFFFFFull));
        g_posidx2[row] = (int)(~(unsigned)(sb2 & 0xFFFFFFFFull));
    }
    __syncthreads();
    for (int i = tid; i < 1024; i += nt) g_bitmap[row * 1024 + i] = bitmap[i];
}

// ---------------- kernel 3: sim = f_nv @ features^T  (TF32 mma.sync tensor cores) ----------------
// C[256,32768] = A[256,2048] x B[32768,2048]^T.  Block 128x128x32, 8 warps (64x32 each),
// 2-stage cp.async pipeline, smem ld=36 (conflict-free fragment gathers).
// Grid = (mTiles=2, nTiles=256): adjacent bids share the N tile -> B read once from DRAM.
#define GLD 36
#define GSTG (128 * GLD)          // floats per (matrix, stage)

__device__ __forceinline__ void mma_tf32(float* c, const float* a, const float* b) {
    asm volatile(
        "mma.sync.aligned.m16n8k8.row.col.f32.tf32.tf32.f32 "
        "{%0,%1,%2,%3}, {%4,%5,%6,%7}, {%8,%9}, {%0,%1,%2,%3};"
        : "+f"(c[0]), "+f"(c[1]), "+f"(c[2]), "+f"(c[3])
        : "r"(__float_as_uint(a[0])), "r"(__float_as_uint(a[1])),
          "r"(__float_as_uint(a[2])), "r"(__float_as_uint(a[3])),
          "r"(__float_as_uint(b[0])), "r"(__float_as_uint(b[1])));
}

__global__ __launch_bounds__(256) void k_gemm(const float* __restrict__ A,   // [256][2048]
                                              const float* __restrict__ B) { // [32768][2048]
    extern __shared__ float smf[];
    float* As = smf;               // [2][128][GLD]
    float* Bs = smf + 2 * GSTG;    // [2][128][GLD]

    const int mBase = blockIdx.x * 128;
    const int nBase = blockIdx.y * 128;
    const int tid  = threadIdx.x;
    const int lane = tid & 31;
    const int wid  = tid >> 5;
    const int wm   = (wid & 1) * 64;   // warp M offset within block
    const int wn   = (wid >> 1) * 32;  // warp N offset within block
    const int lq   = lane >> 2;        // lane/4
    const int lr   = lane & 3;         // lane%4

    float acc[4][4][4];
    #pragma unroll
    for (int i = 0; i < 4; i++)
        #pragma unroll
        for (int j = 0; j < 4; j++)
            #pragma unroll
            for (int r = 0; r < 4; r++) acc[i][j][r] = 0.f;

    // stage loader: A/B tile rows r=0..127, cols k0..k0+31, as 8 float4 per row
    auto issue = [&](int k0, int buf) {
        #pragma unroll
        for (int q = 0; q < 4; q++) {
            int i  = q * 256 + tid;
            int r  = i >> 3;
            int c4 = (i & 7) << 2;
            unsigned sa = (unsigned)__cvta_generic_to_shared(&As[buf * GSTG + r * GLD + c4]);
            unsigned sb = (unsigned)__cvta_generic_to_shared(&Bs[buf * GSTG + r * GLD + c4]);
            const float* ga = A + (size_t)(mBase + r) * DIM + k0 + c4;
            const float* gb = B + (size_t)(nBase + r) * DIM + k0 + c4;
            asm volatile("cp.async.cg.shared.global [%0], [%1], 16;" :: "r"(sa), "l"(ga));
            asm volatile("cp.async.cg.shared.global [%0], [%1], 16;" :: "r"(sb), "l"(gb));
        }
        asm volatile("cp.async.commit_group;");
    };

    issue(0, 0);
    const int nIter = DIM / 32;
    for (int it = 0; it < nIter; it++) {
        int buf = it & 1;
        if (it + 1 < nIter) {
            issue((it + 1) * 32, buf ^ 1);
            asm volatile("cp.async.wait_group 1;");
        } else {
            asm volatile("cp.async.wait_group 0;");
        }
        __syncthreads();

        const float* Ab = As + buf * GSTG;
        const float* Bb = Bs + buf * GSTG;
        #pragma unroll
        for (int kk = 0; kk < 32; kk += 8) {
            float af[4][4], bf[4][2];
            #pragma unroll
            for (int mi = 0; mi < 4; mi++) {
                int m = wm + mi * 16 + lq;
                af[mi][0] = Ab[m * GLD + kk + lr];
                af[mi][1] = Ab[(m + 8) * GLD + kk + lr];
                af[mi][2] = Ab[m * GLD + kk + 4 + lr];
                af[mi][3] = Ab[(m + 8) * GLD + kk + 4 + lr];
            }
            #pragma unroll
            for (int ni = 0; ni < 4; ni++) {
                int n = wn + ni * 8 + lq;
                bf[ni][0] = Bb[n * GLD + kk + lr];
                bf[ni][1] = Bb[n * GLD + kk + 4 + lr];
            }
            #pragma unroll
            for (int mi = 0; mi < 4; mi++)
                #pragma unroll
                for (int ni = 0; ni < 4; ni++)
                    mma_tf32(acc[mi][ni], af[mi], bf[ni]);
        }
        __syncthreads();
    }

    // epilogue: c0,c1 at (lq, 2*lr), c2,c3 at (lq+8, 2*lr)
    #pragma unroll
    for (int mi = 0; mi < 4; mi++) {
        #pragma unroll
        for (int ni = 0; ni < 4; ni++) {
            int m = mBase + wm + mi * 16 + lq;
            int n = nBase + wn + ni * 8 + 2 * lr;
            float2 v0 = make_float2(acc[mi][ni][0], acc[mi][ni][1]);
            float2 v1 = make_float2(acc[mi][ni][2], acc[mi][ni][3]);
            *(float2*)&g_sim[(size_t)m * NBANK + n] = v0;
            *(float2*)&g_sim[(size_t)(m + 8) * NBANK + n] = v1;
        }
    }
}

// ---------------- kernel 4: per-row masked logsumexp + 3 CE terms ----------------
// Iterates only the ~8193+ties set bits per row via __ffs over bitmap words.
__global__ __launch_bounds__(512) void k_loss(const float* __restrict__ f,
                                              const float* __restrict__ f_nv,
                                              const float* __restrict__ feat,
                                              const int* __restrict__ indexes) {
    __shared__ float red[512];
    __shared__ float bmx, bsum;
    const int row = blockIdx.x;
    const int tid = threadIdx.x;
    const int nt  = blockDim.x;
    const float* simr = g_sim + (size_t)row * NBANK;
    const unsigned* bmp = g_bitmap + row * 1024;

    float mx = -1e30f;
    for (int i = tid; i < 1024; i += nt) {
        unsigned w = bmp[i];
        int base = i << 5;
        while (w) {
            int b = __ffs(w) - 1; w &= w - 1;
            mx = fmaxf(mx, simr[base + b]);
        }
    }
    red[tid] = mx; __syncthreads();
    for (int s = nt >> 1; s > 0; s >>= 1) { if (tid < s) red[tid] = fmaxf(red[tid], red[tid + s]); __syncthreads(); }
    if (tid == 0) bmx = red[0];
    __syncthreads();
    mx = bmx;

    float sum = 0.f;
    for (int i = tid; i < 1024; i += nt) {
        unsigned w = bmp[i];
        int base = i << 5;
        while (w) {
            int b = __ffs(w) - 1; w &= w - 1;
            sum += expf((simr[base + b] - mx) / 0.07f);
        }
    }
    __syncthreads();
    red[tid] = sum; __syncthreads();
    for (int s = nt >> 1; s > 0; s >>= 1) { if (tid < s) red[tid] += red[tid + s]; __syncthreads(); }
    if (tid == 0) bsum = red[0];
    __syncthreads();
    sum = bsum;

    // dots: positives_wogan = f[row] . feat[idx1];  l_pos = f_nv[row] . feat[indexes[row]]
    const int idx1 = g_posidx1[row];
    const int bidx = indexes[row];
    const float* frow = f + (size_t)row * DIM;
    const float* fvrow = f_nv + (size_t)row * DIM;
    const float* k1r = feat + (size_t)idx1 * DIM;
    const float* kbr = feat + (size_t)bidx * DIM;
    float d1 = 0.f, d2 = 0.f;
    for (int d = tid; d < DIM; d += nt) { d1 += frow[d] * k1r[d]; d2 += fvrow[d] * kbr[d]; }
    __syncthreads();
    red[tid] = d1; __syncthreads();
    for (int s = nt >> 1; s > 0; s >>= 1) { if (tid < s) red[tid] += red[tid + s]; __syncthreads(); }
    d1 = red[0]; __syncthreads();
    red[tid] = d2; __syncthreads();
    for (int s = nt >> 1; s > 0; s >>= 1) { if (tid < s) red[tid] += red[tid + s]; __syncthreads(); }
    d2 = red[0]; __syncthreads();

    if (tid == 0) {
        float p2 = simr[g_posidx2[row]];
        float c = mx / 0.07f;
        float ce = 0.f;
        float ps[3] = {d2, p2, d1};   // self (l_pos), inter (g2->mat_sim), wogan (g1->mat)
        #pragma unroll
        for (int q = 0; q < 3; q++) {
            float a = ps[q] / 0.07f;
            float M = fmaxf(a, c);
            float l = M + logf(expf(a - M) + sum * expf(c - M));
            ce += l - a;
        }
        g_ce[row] = ce;
    }
}

__global__ void k_final(float* lossOut) {
    __shared__ float red[256];
    int t = threadIdx.x;
    red[t] = g_ce[t]; __syncthreads();
    for (int s = 128; s > 0; s >>= 1) { if (t < s) red[t] += red[t + s]; __syncthreads(); }
    if (t == 0 && lossOut) *lossOut = red[0] / 256.f;
}

// ---------------- kernel 5: momentum update of the 256 touched rows (last-occurrence wins) ----------------
__global__ __launch_bounds__(256) void k_update(const float* __restrict__ f,
                                                const float* __restrict__ feat,
                                                const int* __restrict__ indexes,
                                                float* __restrict__ featOut) {
    const int b = blockIdx.x;
    const int t = threadIdx.x;
    const int idx = indexes[b];
    for (int b2 = b + 1; b2 < BATCH; b2++)
        if (indexes[b2] == idx) return;   // a later write wins; skip (uniform across block)

    __shared__ float red[256];
    const float* kr = feat + (size_t)idx * DIM;
    const float* fr = f + (size_t)b * DIM;
    float u[8]; float ss = 0.f;
    #pragma unroll
    for (int i = 0; i < 8; i++) {
        int d = t + i * 256;
        float v = 0.2f * kr[d] + 0.8f * fr[d];
        u[i] = v; ss += v * v;
    }
    red[t] = ss; __syncthreads();
    for (int s = 128; s > 0; s >>= 1) { if (t < s) red[t] += red[t + s]; __syncthreads(); }
    float den = fmaxf(sqrtf(red[0]), 1e-12f);
    #pragma unroll
    for (int i = 0; i < 8; i++) featOut[(size_t)idx * DIM + t + i * 256] = u[i] / den;
}

// ---------------- launcher ----------------
extern "C" void kernel_launch(void* const* d_in, const int* in_sizes, int n_in,
                              void* d_out, int out_size) {
    const float* f      = (const float*)d_in[0];
    const float* f_nv   = (const float*)d_in[1];
    const float* feat   = (const float*)d_in[2];
    const int*   labels = (const int*)d_in[3];
    const int*   indexes= (const int*)d_in[4];
    (void)in_sizes; (void)n_in;

    float* out = (float*)d_out;
    float* lossOut = out;
    float* featOut = out + 1;                 // pytree order: (loss, new_features)
    const long long nd = (long long)NBANK * DIM;
    if ((long long)out_size == nd) { featOut = out; lossOut = nullptr; }
    else if (out_size == 1)        { featOut = nullptr; }

    const int smemSel = (NBANK + 2048 + 4096 + 1024 + 512) * 4;  // 161792 B
    cudaFuncSetAttribute(k_select, cudaFuncAttributeMaxDynamicSharedMemorySize, smemSel);
    const int smemGemm = 4 * GSTG * (int)sizeof(float);          // 73728 B
    cudaFuncSetAttribute(k_gemm, cudaFuncAttributeMaxDynamicSharedMemorySize, smemGemm);

    if (featOut) {
        int p = (int)((4 - ((((uintptr_t)featOut) >> 2) & 3)) & 3);  // floats to 16B alignment
        k_copy_shift<<<8192, 256>>>(feat, featOut, p);
    }
    k_select<<<BATCH, 512, smemSel>>>(labels, indexes);
    dim3 gg(BATCH / 128, NBANK / 128);        // (mTiles=2, nTiles=256): B-tile L2 reuse
    k_gemm<<<gg, 256, smemGemm>>>(f_nv, feat);
    k_loss<<<BATCH, 512>>>(f, f_nv, feat, indexes);
    if (lossOut) k_final<<<1, 256>>>(lossOut);
    if (featOut) k_update<<<BATCH, 256>>>(f, feat, indexes, featOut);
}

// round 10
// speedup vs baseline: 1.0613x; 1.0613x over previous
#include <cuda_runtime.h>
#include <cstdint>

#define BATCH 256
#define NBANK 32768
#define DIM   2048
#define KSEL  8192

// ---------------- scratch (static device globals; no allocation) ----------------
__device__ float    g_sim[(size_t)BATCH * NBANK];   // 32 MB
__device__ unsigned g_bitmap[BATCH * 1024];         // 1 MB  (32768 bits per row)
__device__ int      g_posidx1[BATCH];               // argmax of g1 (wogan -> mat = f.k)
__device__ int      g_posidx2[BATCH];               // argmax of g2 (-> mat_sim)
__device__ float    g_ce[BATCH];
__device__ float    g_lm[BATCH * 4];                // per-(row, quarter) local max
__device__ float    g_ls[BATCH * 4];                // per-(row, quarter) local sum

// ---------------- threefry2x32 (bit-exact JAX) ----------------
__device__ __forceinline__ void tf2x32(unsigned k0, unsigned k1, unsigned x0, unsigned x1,
                                       unsigned &o0, unsigned &o1) {
    unsigned k2 = k0 ^ k1 ^ 0x1BD11BDAu;
    x0 += k0; x1 += k1;
#define TFR(r) { x0 += x1; x1 = (x1 << (r)) | (x1 >> (32 - (r))); x1 ^= x0; }
    TFR(13) TFR(15) TFR(26) TFR(6)
    x0 += k1; x1 += k2 + 1u;
    TFR(17) TFR(29) TFR(16) TFR(24)
    x0 += k2; x1 += k0 + 2u;
    TFR(13) TFR(15) TFR(26) TFR(6)
    x0 += k0; x1 += k1 + 3u;
    TFR(17) TFR(29) TFR(16) TFR(24)
    x0 += k1; x1 += k2 + 4u;
    TFR(13) TFR(15) TFR(26) TFR(6)
    x0 += k2; x1 += k0 + 5u;
#undef TFR
    o0 = x0; o1 = x1;
}

// jax_threefry_partitionable=True: bits at flat counter c = o0 ^ o1 of TF(key,(0,c)).
__device__ __forceinline__ unsigned rbits32(unsigned k0, unsigned k1, unsigned c) {
    unsigned o0, o1; tf2x32(k0, k1, 0u, c, o0, o1);
    return o0 ^ o1;
}

// ---------------- kernel 1: copy features -> new_features region ----------------
// dst may be misaligned by p floats (0..3). Peel p scalars so dst+p is 16B-aligned,
// then 4 scalar loads + 1 STG.128 per 16 bytes.
__global__ void k_copy_shift(const float* __restrict__ src, float* __restrict__ dst, int p) {
    const size_t n = (size_t)NBANK * DIM;
    const size_t tidg = (size_t)blockIdx.x * blockDim.x + threadIdx.x;
    const size_t stride = (size_t)gridDim.x * blockDim.x;
    if (tidg < (size_t)p) dst[tidg] = src[tidg];          // peel head
    const size_t nv = (n - p) >> 2;                       // # of float4 stores
    float4* __restrict__ dv = (float4*)(dst + p);
    const float* __restrict__ sv = src + p;
    for (size_t i = tidg; i < nv; i += stride) {
        size_t b = i << 2;
        float4 v = make_float4(sv[b], sv[b + 1], sv[b + 2], sv[b + 3]);
        dv[i] = v;
    }
    for (size_t i = p + (nv << 2) + tidg; i < n; i += stride) dst[i] = src[i];  // tail
}

// ---------------- kernel 2: per-row RNG + exact top-K threshold + argmaxes ----------------
// dynamic smem layout (uint32): keys[32768] | hist[2048] | hist2[4096] | bitmap[1024] | gsum[512]
__global__ __launch_bounds__(512) void k_select(const int* __restrict__ labels,
                                                const int* __restrict__ indexes) {
    extern __shared__ unsigned sm[];
    unsigned* keys   = sm;
    unsigned* hist   = keys + NBANK;
    unsigned* hist2  = hist + 2048;
    unsigned* bitmap = hist2 + 4096;
    unsigned* gsum   = bitmap + 1024;

    __shared__ unsigned long long sb1, sb2;
    __shared__ int sBin, sCab, sMneed, eqn;
    __shared__ unsigned sT;
    __shared__ int eqlist[128];

    const int row = blockIdx.x;
    const int tid = threadIdx.x;
    const int nt  = blockDim.x;

    // foldlike split: kg_i = (o0,o1) of threefry((0,42),(0,i))
    unsigned K1a, K1b, K2a, K2b, K3a, K3b;
    tf2x32(0u, 42u, 0u, 0u, K1a, K1b);
    tf2x32(0u, 42u, 0u, 1u, K2a, K2b);
    tf2x32(0u, 42u, 0u, 2u, K3a, K3b);

    const int bl = labels[indexes[row]];

    if (tid == 0) { sb1 = 0ull; sb2 = 0ull; eqn = 0; }
    for (int i = tid; i < 2048 + 4096 + 1024 + 512; i += nt) hist[i] = 0u;
    __syncthreads();

    // pass 1: keys + histogram (negatives) + g1/g2 argmax (positives only)
    unsigned long long b1 = 0ull, b2 = 0ull;
    for (int j = tid; j < NBANK; j += nt) {
        unsigned flat = (unsigned)(row * NBANK + j);
        unsigned kk;
        if (labels[j] == bl) {
            unsigned m1 = rbits32(K1a, K1b, flat) >> 9;
            unsigned m2 = rbits32(K2a, K2b, flat) >> 9;
            unsigned nj = ~(unsigned)j;   // tie-break: larger ~j == smaller j
            unsigned long long s1 = ((unsigned long long)(m1 + 1u) << 32) | nj;
            unsigned long long s2 = ((unsigned long long)(m2 + 1u) << 32) | nj;
            if (s1 > b1) b1 = s1;
            if (s2 > b2) b2 = s2;
            kk = 0xFFFFFFFFu;             // sentinel: positive, excluded from top-K
        } else {
            unsigned m3 = rbits32(K3a, K3b, flat) >> 9;   // 23-bit key, monotone with gumbel
            atomicAdd(&hist[m3 >> 12], 1u);
            kk = m3;
        }
        keys[j] = kk;
    }
    atomicMax(&sb1, b1);
    atomicMax(&sb2, b2);
    __syncthreads();

    // level-1 threshold search over 2048 bins (groups of 8)
    if (tid < 256) {
        unsigned s = 0;
        #pragma unroll
        for (int i = 0; i < 8; i++) s += hist[tid * 8 + i];
        gsum[tid] = s;
    }
    __syncthreads();
    if (tid == 0) {
        unsigned acc = 0; int bin = -1;
        for (int g = 255; g >= 0; --g) {
            if (acc + gsum[g] >= (unsigned)KSEL) {
                for (int bb = g * 8 + 7;; --bb) {
                    if (acc + hist[bb] >= (unsigned)KSEL) { bin = bb; break; }
                    acc += hist[bb];
                }
                break;
            }
            acc += gsum[g];
        }
        sBin = bin; sCab = (int)acc;   // acc = count of keys strictly above bin
    }
    __syncthreads();
    const int bin = sBin;

    // level-2: refine within the threshold bin (low 12 bits)
    for (int j = tid; j < NBANK; j += nt) {
        unsigned kk = keys[j];
        if (kk != 0xFFFFFFFFu && (int)(kk >> 12) == bin) atomicAdd(&hist2[kk & 0xFFF], 1u);
    }
    __syncthreads();
    if (tid < 512) {
        unsigned s = 0;
        #pragma unroll
        for (int i = 0; i < 8; i++) s += hist2[tid * 8 + i];
        gsum[tid] = s;
    }
    __syncthreads();
    if (tid == 0) {
        unsigned acc = (unsigned)sCab; int v = -1;
        for (int g = 511; g >= 0; --g) {
            if (acc + gsum[g] >= (unsigned)KSEL) {
                for (int bb = g * 8 + 7;; --bb) {
                    if (acc + hist2[bb] >= (unsigned)KSEL) { v = bb; break; }
                    acc += hist2[bb];
                }
                break;
            }
            acc += gsum[g];
        }
        sT = ((unsigned)bin << 12) | (unsigned)v;   // exact 23-bit threshold
        sMneed = KSEL - (int)acc;                   // # of ==T elems, lowest index first
    }
    __syncthreads();
    const unsigned T = sT;

    // pass 3: bitmap of strictly-greater; collect ==T candidates
    for (int j = tid; j < NBANK; j += nt) {
        unsigned kk = keys[j];
        if (kk == 0xFFFFFFFFu) continue;
        if (kk > T) {
            atomicOr(&bitmap[j >> 5], 1u << (j & 31));
        } else if (kk == T) {
            int p = atomicAdd(&eqn, 1);
            if (p < 128) eqlist[p] = j;
        }
    }
    __syncthreads();
    if (tid == 0) {
        int n = eqn; if (n > 128) n = 128;
        for (int a = 1; a < n; a++) {              // sort ascending (n is tiny)
            int x = eqlist[a], c = a - 1;
            while (c >= 0 && eqlist[c] > x) { eqlist[c + 1] = eqlist[c]; c--; }
            eqlist[c + 1] = x;
        }
        int m = sMneed; if (m > n) m = n;
        for (int a = 0; a < m; a++) { int j = eqlist[a]; bitmap[j >> 5] |= 1u << (j & 31); }
        g_posidx1[row] = (int)(~(unsigned)(sb1 & 0xFFFFFFFFull));
        g_posidx2[row] = (int)(~(unsigned)(sb2 & 0xFFFFFFFFull));
    }
    __syncthreads();
    for (int i = tid; i < 1024; i += nt) g_bitmap[row * 1024 + i] = bitmap[i];
}

// ---------------- kernel 3: sim = f_nv @ features^T  (TF32 mma.sync tensor cores) ----------------
// C[256,32768] = A[256,2048] x B[32768,2048]^T.  Block 128x128x32, 8 warps (64x32 each),
// 2-stage cp.async pipeline, smem ld=36 (conflict-free fragment gathers).
// Grid = (mTiles=2, nTiles=256): adjacent bids share the N tile -> B read once from DRAM.
#define GLD 36
#define GSTG (128 * GLD)          // floats per (matrix, stage)

__device__ __forceinline__ void mma_tf32(float* c, const float* a, const float* b) {
    asm volatile(
        "mma.sync.aligned.m16n8k8.row.col.f32.tf32.tf32.f32 "
        "{%0,%1,%2,%3}, {%4,%5,%6,%7}, {%8,%9}, {%0,%1,%2,%3};"
        : "+f"(c[0]), "+f"(c[1]), "+f"(c[2]), "+f"(c[3])
        : "r"(__float_as_uint(a[0])), "r"(__float_as_uint(a[1])),
          "r"(__float_as_uint(a[2])), "r"(__float_as_uint(a[3])),
          "r"(__float_as_uint(b[0])), "r"(__float_as_uint(b[1])));
}

__global__ __launch_bounds__(256) void k_gemm(const float* __restrict__ A,   // [256][2048]
                                              const float* __restrict__ B) { // [32768][2048]
    extern __shared__ float smf[];
    float* As = smf;               // [2][128][GLD]
    float* Bs = smf + 2 * GSTG;    // [2][128][GLD]

    const int mBase = blockIdx.x * 128;
    const int nBase = blockIdx.y * 128;
    const int tid  = threadIdx.x;
    const int lane = tid & 31;
    const int wid  = tid >> 5;
    const int wm   = (wid & 1) * 64;   // warp M offset within block
    const int wn   = (wid >> 1) * 32;  // warp N offset within block
    const int lq   = lane >> 2;        // lane/4
    const int lr   = lane & 3;         // lane%4

    float acc[4][4][4];
    #pragma unroll
    for (int i = 0; i < 4; i++)
        #pragma unroll
        for (int j = 0; j < 4; j++)
            #pragma unroll
            for (int r = 0; r < 4; r++) acc[i][j][r] = 0.f;

    // stage loader: A/B tile rows r=0..127, cols k0..k0+31, as 8 float4 per row
    auto issue = [&](int k0, int buf) {
        #pragma unroll
        for (int q = 0; q < 4; q++) {
            int i  = q * 256 + tid;
            int r  = i >> 3;
            int c4 = (i & 7) << 2;
            unsigned sa = (unsigned)__cvta_generic_to_shared(&As[buf * GSTG + r * GLD + c4]);
            unsigned sb = (unsigned)__cvta_generic_to_shared(&Bs[buf * GSTG + r * GLD + c4]);
            const float* ga = A + (size_t)(mBase + r) * DIM + k0 + c4;
            const float* gb = B + (size_t)(nBase + r) * DIM + k0 + c4;
            asm volatile("cp.async.cg.shared.global [%0], [%1], 16;" :: "r"(sa), "l"(ga));
            asm volatile("cp.async.cg.shared.global [%0], [%1], 16;" :: "r"(sb), "l"(gb));
        }
        asm volatile("cp.async.commit_group;");
    };

    issue(0, 0);
    const int nIter = DIM / 32;
    for (int it = 0; it < nIter; it++) {
        int buf = it & 1;
        if (it + 1 < nIter) {
            issue((it + 1) * 32, buf ^ 1);
            asm volatile("cp.async.wait_group 1;");
        } else {
            asm volatile("cp.async.wait_group 0;");
        }
        __syncthreads();

        const float* Ab = As + buf * GSTG;
        const float* Bb = Bs + buf * GSTG;
        #pragma unroll
        for (int kk = 0; kk < 32; kk += 8) {
            float af[4][4], bf[4][2];
            #pragma unroll
            for (int mi = 0; mi < 4; mi++) {
                int m = wm + mi * 16 + lq;
                af[mi][0] = Ab[m * GLD + kk + lr];
                af[mi][1] = Ab[(m + 8) * GLD + kk + lr];
                af[mi][2] = Ab[m * GLD + kk + 4 + lr];
                af[mi][3] = Ab[(m + 8) * GLD + kk + 4 + lr];
            }
            #pragma unroll
            for (int ni = 0; ni < 4; ni++) {
                int n = wn + ni * 8 + lq;
                bf[ni][0] = Bb[n * GLD + kk + lr];
                bf[ni][1] = Bb[n * GLD + kk + 4 + lr];
            }
            #pragma unroll
            for (int mi = 0; mi < 4; mi++)
                #pragma unroll
                for (int ni = 0; ni < 4; ni++)
                    mma_tf32(acc[mi][ni], af[mi], bf[ni]);
        }
        __syncthreads();
    }

    // epilogue: c0,c1 at (lq, 2*lr), c2,c3 at (lq+8, 2*lr)
    #pragma unroll
    for (int mi = 0; mi < 4; mi++) {
        #pragma unroll
        for (int ni = 0; ni < 4; ni++) {
            int m = mBase + wm + mi * 16 + lq;
            int n = nBase + wn + ni * 8 + 2 * lr;
            float2 v0 = make_float2(acc[mi][ni][0], acc[mi][ni][1]);
            float2 v1 = make_float2(acc[mi][ni][2], acc[mi][ni][3]);
            *(float2*)&g_sim[(size_t)m * NBANK + n] = v0;
            *(float2*)&g_sim[(size_t)(m + 8) * NBANK + n] = v1;
        }
    }
}

// ---------------- kernel 4a: per-(row, quarter) masked max+sum (1024 blocks) ----------------
__global__ __launch_bounds__(256) void k_lse() {
    __shared__ float red[256];
    const int row = blockIdx.x >> 2;
    const int qtr = blockIdx.x & 3;
    const int tid = threadIdx.x;
    const float* simr = g_sim + (size_t)row * NBANK + qtr * 8192;
    const unsigned* bmp = g_bitmap + row * 1024 + qtr * 256;

    float mx = -1e30f;
    {
        unsigned w = bmp[tid];
        int base = tid << 5;
        while (w) {
            int b = __ffs(w) - 1; w &= w - 1;
            mx = fmaxf(mx, simr[base + b]);
        }
    }
    red[tid] = mx; __syncthreads();
    for (int s = 128; s > 0; s >>= 1) { if (tid < s) red[tid] = fmaxf(red[tid], red[tid + s]); __syncthreads(); }
    mx = red[0]; __syncthreads();

    float sum = 0.f;
    {
        unsigned w = bmp[tid];
        int base = tid << 5;
        while (w) {
            int b = __ffs(w) - 1; w &= w - 1;
            sum += expf((simr[base + b] - mx) / 0.07f);
        }
    }
    red[tid] = sum; __syncthreads();
    for (int s = 128; s > 0; s >>= 1) { if (tid < s) red[tid] += red[tid + s]; __syncthreads(); }
    if (tid == 0) { g_lm[row * 4 + qtr] = mx; g_ls[row * 4 + qtr] = red[0]; }
}

// ---------------- kernel 4b: merge quarters + dots + 3 CE terms (256 blocks) ----------------
__global__ __launch_bounds__(256) void k_ce(const float* __restrict__ f,
                                            const float* __restrict__ f_nv,
                                            const float* __restrict__ feat,
                                            const int* __restrict__ indexes) {
    __shared__ float red[256];
    __shared__ float sM, sS;
    const int row = blockIdx.x;
    const int tid = threadIdx.x;

    if (tid == 0) {
        float M = -1e30f;
        #pragma unroll
        for (int i = 0; i < 4; i++) M = fmaxf(M, g_lm[row * 4 + i]);
        float S = 0.f;
        #pragma unroll
        for (int i = 0; i < 4; i++) S += g_ls[row * 4 + i] * expf((g_lm[row * 4 + i] - M) / 0.07f);
        sM = M; sS = S;
    }

    // dots: positives_wogan = f[row] . feat[idx1];  l_pos = f_nv[row] . feat[indexes[row]]
    const int idx1 = g_posidx1[row];
    const int bidx = indexes[row];
    const float* frow = f + (size_t)row * DIM;
    const float* fvrow = f_nv + (size_t)row * DIM;
    const float* k1r = feat + (size_t)idx1 * DIM;
    const float* kbr = feat + (size_t)bidx * DIM;
    float d1 = 0.f, d2 = 0.f;
    for (int d = tid; d < DIM; d += 256) { d1 += frow[d] * k1r[d]; d2 += fvrow[d] * kbr[d]; }
    red[tid] = d1; __syncthreads();
    for (int s = 128; s > 0; s >>= 1) { if (tid < s) red[tid] += red[tid + s]; __syncthreads(); }
    d1 = red[0]; __syncthreads();
    red[tid] = d2; __syncthreads();
    for (int s = 128; s > 0; s >>= 1) { if (tid < s) red[tid] += red[tid + s]; __syncthreads(); }
    d2 = red[0]; __syncthreads();

    if (tid == 0) {
        const float* simr = g_sim + (size_t)row * NBANK;
        float p2 = simr[g_posidx2[row]];
        float c = sM / 0.07f;
        float sum = sS;
        float ce = 0.f;
        float ps[3] = {d2, p2, d1};   // self (l_pos), inter (g2->mat_sim), wogan (g1->mat)
        #pragma unroll
        for (int q = 0; q < 3; q++) {
            float a = ps[q] / 0.07f;
            float M2 = fmaxf(a, c);
            float l = M2 + logf(expf(a - M2) + sum * expf(c - M2));
            ce += l - a;
        }
        g_ce[row] = ce;
    }
}

__global__ void k_final(float* lossOut) {
    __shared__ float red[256];
    int t = threadIdx.x;
    red[t] = g_ce[t]; __syncthreads();
    for (int s = 128; s > 0; s >>= 1) { if (t < s) red[t] += red[t + s]; __syncthreads(); }
    if (t == 0 && lossOut) *lossOut = red[0] / 256.f;
}

// ---------------- kernel 5: momentum update of the 256 touched rows (last-occurrence wins) ----------------
__global__ __launch_bounds__(256) void k_update(const float* __restrict__ f,
                                                const float* __restrict__ feat,
                                                const int* __restrict__ indexes,
                                                float* __restrict__ featOut) {
    const int b = blockIdx.x;
    const int t = threadIdx.x;
    const int idx = indexes[b];
    for (int b2 = b + 1; b2 < BATCH; b2++)
        if (indexes[b2] == idx) return;   // a later write wins; skip (uniform across block)

    __shared__ float red[256];
    const float* kr = feat + (size_t)idx * DIM;
    const float* fr = f + (size_t)b * DIM;
    float u[8]; float ss = 0.f;
    #pragma unroll
    for (int i = 0; i < 8; i++) {
        int d = t + i * 256;
        float v = 0.2f * kr[d] + 0.8f * fr[d];
        u[i] = v; ss += v * v;
    }
    red[t] = ss; __syncthreads();
    for (int s = 128; s > 0; s >>= 1) { if (t < s) red[t] += red[t + s]; __syncthreads(); }
    float den = fmaxf(sqrtf(red[0]), 1e-12f);
    #pragma unroll
    for (int i = 0; i < 8; i++) featOut[(size_t)idx * DIM + t + i * 256] = u[i] / den;
}

// ---------------- launcher ----------------
// Stream/events are created ONCE on the first (uncaptured correctness) call and
// reused thereafter; every call performs identical work on identical inputs.
// Graph fork/join: s2 = {copy -> select}, main = {gemm}; join before k_lse
// (needs select's bitmap + gemm's sim) and before k_update (needs copy).
extern "C" void kernel_launch(void* const* d_in, const int* in_sizes, int n_in,
                              void* d_out, int out_size) {
    const float* f      = (const float*)d_in[0];
    const float* f_nv   = (const float*)d_in[1];
    const float* feat   = (const float*)d_in[2];
    const int*   labels = (const int*)d_in[3];
    const int*   indexes= (const int*)d_in[4];
    (void)in_sizes; (void)n_in;

    float* out = (float*)d_out;
    float* lossOut = out;
    float* featOut = out + 1;                 // pytree order: (loss, new_features)
    const long long nd = (long long)NBANK * DIM;
    if ((long long)out_size == nd) { featOut = out; lossOut = nullptr; }
    else if (out_size == 1)        { featOut = nullptr; }

    static cudaStream_t s2 = nullptr;
    static cudaEvent_t evFork = nullptr, evJoin = nullptr, evSel = nullptr;
    if (!s2) {
        cudaStreamCreateWithFlags(&s2, cudaStreamNonBlocking);
        cudaEventCreateWithFlags(&evFork, cudaEventDisableTiming);
        cudaEventCreateWithFlags(&evJoin, cudaEventDisableTiming);
        cudaEventCreateWithFlags(&evSel, cudaEventDisableTiming);
    }

    const int smemSel = (NBANK + 2048 + 4096 + 1024 + 512) * 4;  // 161792 B
    cudaFuncSetAttribute(k_select, cudaFuncAttributeMaxDynamicSharedMemorySize, smemSel);
    const int smemGemm = 4 * GSTG * (int)sizeof(float);          // 73728 B
    cudaFuncSetAttribute(k_gemm, cudaFuncAttributeMaxDynamicSharedMemorySize, smemGemm);

    // fork: s2 runs {copy (if needed) -> select}, overlapped with gemm on main
    cudaEventRecord(evFork, 0);
    cudaStreamWaitEvent(s2, evFork, 0);
    if (featOut) {
        int p = (int)((4 - ((((uintptr_t)featOut) >> 2) & 3)) & 3);  // floats to 16B alignment
        k_copy_shift<<<8192, 256, 0, s2>>>(feat, featOut, p);
        cudaEventRecord(evJoin, s2);
    }
    k_select<<<BATCH, 512, smemSel, s2>>>(labels, indexes);
    cudaEventRecord(evSel, s2);

    dim3 gg(BATCH / 128, NBANK / 128);        // (mTiles=2, nTiles=256): B-tile L2 reuse
    k_gemm<<<gg, 256, smemGemm>>>(f_nv, feat);

    cudaStreamWaitEvent(0, evSel, 0);         // join: select results needed below
    k_lse<<<BATCH * 4, 256>>>();
    k_ce<<<BATCH, 256>>>(f, f_nv, feat, indexes);
    if (lossOut) k_final<<<1, 256>>>(lossOut);

    if (featOut) {
        cudaStreamWaitEvent(0, evJoin, 0);    // join: copy must land before row updates
        k_update<<<BATCH, 256>>>(f, feat, indexes, featOut);
    }
}

// round 11
// speedup vs baseline: 1.0685x; 1.0068x over previous
#include <cuda_runtime.h>
#include <cstdint>

#define BATCH 256
#define NBANK 32768
#define DIM   2048
#define KSEL  8192

// ---------------- scratch (static device globals; no allocation) ----------------
__device__ float    g_sim[(size_t)BATCH * NBANK];   // 32 MB
__device__ unsigned g_bitmap[BATCH * 1024];         // 1 MB  (32768 bits per row)
__device__ int      g_posidx1[BATCH];               // argmax of g1 (wogan -> mat = f.k)
__device__ int      g_posidx2[BATCH];               // argmax of g2 (-> mat_sim)
__device__ float    g_ce[BATCH];
__device__ float    g_lm[BATCH * 4];                // per-(row, quarter) local max
__device__ float    g_ls[BATCH * 4];                // per-(row, quarter) local sum

// ---------------- threefry2x32 (bit-exact JAX) ----------------
__device__ __forceinline__ void tf2x32(unsigned k0, unsigned k1, unsigned x0, unsigned x1,
                                       unsigned &o0, unsigned &o1) {
    unsigned k2 = k0 ^ k1 ^ 0x1BD11BDAu;
    x0 += k0; x1 += k1;
#define TFR(r) { x0 += x1; x1 = (x1 << (r)) | (x1 >> (32 - (r))); x1 ^= x0; }
    TFR(13) TFR(15) TFR(26) TFR(6)
    x0 += k1; x1 += k2 + 1u;
    TFR(17) TFR(29) TFR(16) TFR(24)
    x0 += k2; x1 += k0 + 2u;
    TFR(13) TFR(15) TFR(26) TFR(6)
    x0 += k0; x1 += k1 + 3u;
    TFR(17) TFR(29) TFR(16) TFR(24)
    x0 += k1; x1 += k2 + 4u;
    TFR(13) TFR(15) TFR(26) TFR(6)
    x0 += k2; x1 += k0 + 5u;
#undef TFR
    o0 = x0; o1 = x1;
}

// jax_threefry_partitionable=True: bits at flat counter c = o0 ^ o1 of TF(key,(0,c)).
__device__ __forceinline__ unsigned rbits32(unsigned k0, unsigned k1, unsigned c) {
    unsigned o0, o1; tf2x32(k0, k1, 0u, c, o0, o1);
    return o0 ^ o1;
}

// ---------------- kernel 1: copy features -> new_features region ----------------
// dst may be misaligned by p floats (0..3). Peel p scalars so dst+p is 16B-aligned,
// then 4 scalar loads + 1 STG.128 per 16 bytes.
__global__ void k_copy_shift(const float* __restrict__ src, float* __restrict__ dst, int p) {
    const size_t n = (size_t)NBANK * DIM;
    const size_t tidg = (size_t)blockIdx.x * blockDim.x + threadIdx.x;
    const size_t stride = (size_t)gridDim.x * blockDim.x;
    if (tidg < (size_t)p) dst[tidg] = src[tidg];          // peel head
    const size_t nv = (n - p) >> 2;                       // # of float4 stores
    float4* __restrict__ dv = (float4*)(dst + p);
    const float* __restrict__ sv = src + p;
    for (size_t i = tidg; i < nv; i += stride) {
        size_t b = i << 2;
        float4 v = make_float4(sv[b], sv[b + 1], sv[b + 2], sv[b + 3]);
        dv[i] = v;
    }
    for (size_t i = p + (nv << 2) + tidg; i < n; i += stride) dst[i] = src[i];  // tail
}

// ---------------- kernel 2: per-row RNG + exact top-K threshold + argmaxes ----------------
// dynamic smem layout (uint32): keys[32768] | hist[2048] | hist2[4096] | bitmap[1024] | gsum[512]
__global__ __launch_bounds__(512) void k_select(const int* __restrict__ labels,
                                                const int* __restrict__ indexes) {
    extern __shared__ unsigned sm[];
    unsigned* keys   = sm;
    unsigned* hist   = keys + NBANK;
    unsigned* hist2  = hist + 2048;
    unsigned* bitmap = hist2 + 4096;
    unsigned* gsum   = bitmap + 1024;

    __shared__ unsigned long long sb1, sb2;
    __shared__ int sBin, sCab, sMneed, eqn;
    __shared__ unsigned sT;
    __shared__ int eqlist[128];

    const int row = blockIdx.x;
    const int tid = threadIdx.x;
    const int nt  = blockDim.x;

    // foldlike split: kg_i = (o0,o1) of threefry((0,42),(0,i))
    unsigned K1a, K1b, K2a, K2b, K3a, K3b;
    tf2x32(0u, 42u, 0u, 0u, K1a, K1b);
    tf2x32(0u, 42u, 0u, 1u, K2a, K2b);
    tf2x32(0u, 42u, 0u, 2u, K3a, K3b);

    const int bl = labels[indexes[row]];

    if (tid == 0) { sb1 = 0ull; sb2 = 0ull; eqn = 0; }
    for (int i = tid; i < 2048 + 4096 + 1024 + 512; i += nt) hist[i] = 0u;
    __syncthreads();

    // pass 1: keys + histogram (negatives) + g1/g2 argmax (positives only)
    unsigned long long b1 = 0ull, b2 = 0ull;
    for (int j = tid; j < NBANK; j += nt) {
        unsigned flat = (unsigned)(row * NBANK + j);
        unsigned kk;
        if (labels[j] == bl) {
            unsigned m1 = rbits32(K1a, K1b, flat) >> 9;
            unsigned m2 = rbits32(K2a, K2b, flat) >> 9;
            unsigned nj = ~(unsigned)j;   // tie-break: larger ~j == smaller j
            unsigned long long s1 = ((unsigned long long)(m1 + 1u) << 32) | nj;
            unsigned long long s2 = ((unsigned long long)(m2 + 1u) << 32) | nj;
            if (s1 > b1) b1 = s1;
            if (s2 > b2) b2 = s2;
            kk = 0xFFFFFFFFu;             // sentinel: positive, excluded from top-K
        } else {
            unsigned m3 = rbits32(K3a, K3b, flat) >> 9;   // 23-bit key, monotone with gumbel
            atomicAdd(&hist[m3 >> 12], 1u);
            kk = m3;
        }
        keys[j] = kk;
    }
    atomicMax(&sb1, b1);
    atomicMax(&sb2, b2);
    __syncthreads();

    // level-1 threshold search over 2048 bins (groups of 8)
    if (tid < 256) {
        unsigned s = 0;
        #pragma unroll
        for (int i = 0; i < 8; i++) s += hist[tid * 8 + i];
        gsum[tid] = s;
    }
    __syncthreads();
    if (tid == 0) {
        unsigned acc = 0; int bin = -1;
        for (int g = 255; g >= 0; --g) {
            if (acc + gsum[g] >= (unsigned)KSEL) {
                for (int bb = g * 8 + 7;; --bb) {
                    if (acc + hist[bb] >= (unsigned)KSEL) { bin = bb; break; }
                    acc += hist[bb];
                }
                break;
            }
            acc += gsum[g];
        }
        sBin = bin; sCab = (int)acc;   // acc = count of keys strictly above bin
    }
    __syncthreads();
    const int bin = sBin;

    // level-2: refine within the threshold bin (low 12 bits)
    for (int j = tid; j < NBANK; j += nt) {
        unsigned kk = keys[j];
        if (kk != 0xFFFFFFFFu && (int)(kk >> 12) == bin) atomicAdd(&hist2[kk & 0xFFF], 1u);
    }
    __syncthreads();
    if (tid < 512) {
        unsigned s = 0;
        #pragma unroll
        for (int i = 0; i < 8; i++) s += hist2[tid * 8 + i];
        gsum[tid] = s;
    }
    __syncthreads();
    if (tid == 0) {
        unsigned acc = (unsigned)sCab; int v = -1;
        for (int g = 511; g >= 0; --g) {
            if (acc + gsum[g] >= (unsigned)KSEL) {
                for (int bb = g * 8 + 7;; --bb) {
                    if (acc + hist2[bb] >= (unsigned)KSEL) { v = bb; break; }
                    acc += hist2[bb];
                }
                break;
            }
            acc += gsum[g];
        }
        sT = ((unsigned)bin << 12) | (unsigned)v;   // exact 23-bit threshold
        sMneed = KSEL - (int)acc;                   // # of ==T elems, lowest index first
    }
    __syncthreads();
    const unsigned T = sT;

    // pass 3: bitmap of strictly-greater; collect ==T candidates
    for (int j = tid; j < NBANK; j += nt) {
        unsigned kk = keys[j];
        if (kk == 0xFFFFFFFFu) continue;
        if (kk > T) {
            atomicOr(&bitmap[j >> 5], 1u << (j & 31));
        } else if (kk == T) {
            int p = atomicAdd(&eqn, 1);
            if (p < 128) eqlist[p] = j;
        }
    }
    __syncthreads();
    if (tid == 0) {
        int n = eqn; if (n > 128) n = 128;
        for (int a = 1; a < n; a++) {              // sort ascending (n is tiny)
            int x = eqlist[a], c = a - 1;
            while (c >= 0 && eqlist[c] > x) { eqlist[c + 1] = eqlist[c]; c--; }
            eqlist[c + 1] = x;
        }
        int m = sMneed; if (m > n) m = n;
        for (int a = 0; a < m; a++) { int j = eqlist[a]; bitmap[j >> 5] |= 1u << (j & 31); }
        g_posidx1[row] = (int)(~(unsigned)(sb1 & 0xFFFFFFFFull));
        g_posidx2[row] = (int)(~(unsigned)(sb2 & 0xFFFFFFFFull));
    }
    __syncthreads();
    for (int i = tid; i < 1024; i += nt) g_bitmap[row * 1024 + i] = bitmap[i];
}

// ---------------- kernel 3: sim = f_nv @ features^T  (TF32 mma.sync tensor cores) ----------------
// C[256,32768] = A[256,2048] x B[32768,2048]^T.  Block 128x128x32, 8 warps (64x32 each),
// 2-stage cp.async pipeline, smem ld=36 (conflict-free fragment gathers).
// Grid = (mTiles=2, nTiles=256): adjacent bids share the N tile -> B read once from DRAM.
// __launch_bounds__(256, 2): cap regs at 128 so 2 CTAs/SM co-reside (latency-bound fix).
#define GLD 36
#define GSTG (128 * GLD)          // floats per (matrix, stage)

__device__ __forceinline__ void mma_tf32(float* c, const float* a, const float* b) {
    asm volatile(
        "mma.sync.aligned.m16n8k8.row.col.f32.tf32.tf32.f32 "
        "{%0,%1,%2,%3}, {%4,%5,%6,%7}, {%8,%9}, {%0,%1,%2,%3};"
        : "+f"(c[0]), "+f"(c[1]), "+f"(c[2]), "+f"(c[3])
        : "r"(__float_as_uint(a[0])), "r"(__float_as_uint(a[1])),
          "r"(__float_as_uint(a[2])), "r"(__float_as_uint(a[3])),
          "r"(__float_as_uint(b[0])), "r"(__float_as_uint(b[1])));
}

__global__ __launch_bounds__(256, 2) void k_gemm(const float* __restrict__ A,   // [256][2048]
                                                 const float* __restrict__ B) { // [32768][2048]
    extern __shared__ float smf[];
    float* As = smf;               // [2][128][GLD]
    float* Bs = smf + 2 * GSTG;    // [2][128][GLD]

    const int mBase = blockIdx.x * 128;
    const int nBase = blockIdx.y * 128;
    const int tid  = threadIdx.x;
    const int lane = tid & 31;
    const int wid  = tid >> 5;
    const int wm   = (wid & 1) * 64;   // warp M offset within block
    const int wn   = (wid >> 1) * 32;  // warp N offset within block
    const int lq   = lane >> 2;        // lane/4
    const int lr   = lane & 3;         // lane%4

    float acc[4][4][4];
    #pragma unroll
    for (int i = 0; i < 4; i++)
        #pragma unroll
        for (int j = 0; j < 4; j++)
            #pragma unroll
            for (int r = 0; r < 4; r++) acc[i][j][r] = 0.f;

    // stage loader: A/B tile rows r=0..127, cols k0..k0+31, as 8 float4 per row
    auto issue = [&](int k0, int buf) {
        #pragma unroll
        for (int q = 0; q < 4; q++) {
            int i  = q * 256 + tid;
            int r  = i >> 3;
            int c4 = (i & 7) << 2;
            unsigned sa = (unsigned)__cvta_generic_to_shared(&As[buf * GSTG + r * GLD + c4]);
            unsigned sb = (unsigned)__cvta_generic_to_shared(&Bs[buf * GSTG + r * GLD + c4]);
            const float* ga = A + (size_t)(mBase + r) * DIM + k0 + c4;
            const float* gb = B + (size_t)(nBase + r) * DIM + k0 + c4;
            asm volatile("cp.async.cg.shared.global [%0], [%1], 16;" :: "r"(sa), "l"(ga));
            asm volatile("cp.async.cg.shared.global [%0], [%1], 16;" :: "r"(sb), "l"(gb));
        }
        asm volatile("cp.async.commit_group;");
    };

    issue(0, 0);
    const int nIter = DIM / 32;
    for (int it = 0; it < nIter; it++) {
        int buf = it & 1;
        if (it + 1 < nIter) {
            issue((it + 1) * 32, buf ^ 1);
            asm volatile("cp.async.wait_group 1;");
        } else {
            asm volatile("cp.async.wait_group 0;");
        }
        __syncthreads();

        const float* Ab = As + buf * GSTG;
        const float* Bb = Bs + buf * GSTG;
        #pragma unroll
        for (int kk = 0; kk < 32; kk += 8) {
            float af[4][4], bf[4][2];
            #pragma unroll
            for (int mi = 0; mi < 4; mi++) {
                int m = wm + mi * 16 + lq;
                af[mi][0] = Ab[m * GLD + kk + lr];
                af[mi][1] = Ab[(m + 8) * GLD + kk + lr];
                af[mi][2] = Ab[m * GLD + kk + 4 + lr];
                af[mi][3] = Ab[(m + 8) * GLD + kk + 4 + lr];
            }
            #pragma unroll
            for (int ni = 0; ni < 4; ni++) {
                int n = wn + ni * 8 + lq;
                bf[ni][0] = Bb[n * GLD + kk + lr];
                bf[ni][1] = Bb[n * GLD + kk + 4 + lr];
            }
            #pragma unroll
            for (int mi = 0; mi < 4; mi++)
                #pragma unroll
                for (int ni = 0; ni < 4; ni++)
                    mma_tf32(acc[mi][ni], af[mi], bf[ni]);
        }
        __syncthreads();
    }

    // epilogue: c0,c1 at (lq, 2*lr), c2,c3 at (lq+8, 2*lr)
    #pragma unroll
    for (int mi = 0; mi < 4; mi++) {
        #pragma unroll
        for (int ni = 0; ni < 4; ni++) {
            int m = mBase + wm + mi * 16 + lq;
            int n = nBase + wn + ni * 8 + 2 * lr;
            float2 v0 = make_float2(acc[mi][ni][0], acc[mi][ni][1]);
            float2 v1 = make_float2(acc[mi][ni][2], acc[mi][ni][3]);
            *(float2*)&g_sim[(size_t)m * NBANK + n] = v0;
            *(float2*)&g_sim[(size_t)(m + 8) * NBANK + n] = v1;
        }
    }
}

// ---------------- kernel 4a: per-(row, quarter) masked max+sum (1024 blocks) ----------------
__global__ __launch_bounds__(256) void k_lse() {
    __shared__ float red[256];
    const int row = blockIdx.x >> 2;
    const int qtr = blockIdx.x & 3;
    const int tid = threadIdx.x;
    const float* simr = g_sim + (size_t)row * NBANK + qtr * 8192;
    const unsigned* bmp = g_bitmap + row * 1024 + qtr * 256;

    float mx = -1e30f;
    {
        unsigned w = bmp[tid];
        int base = tid << 5;
        while (w) {
            int b = __ffs(w) - 1; w &= w - 1;
            mx = fmaxf(mx, simr[base + b]);
        }
    }
    red[tid] = mx; __syncthreads();
    for (int s = 128; s > 0; s >>= 1) { if (tid < s) red[tid] = fmaxf(red[tid], red[tid + s]); __syncthreads(); }
    mx = red[0]; __syncthreads();

    float sum = 0.f;
    {
        unsigned w = bmp[tid];
        int base = tid << 5;
        while (w) {
            int b = __ffs(w) - 1; w &= w - 1;
            sum += expf((simr[base + b] - mx) / 0.07f);
        }
    }
    red[tid] = sum; __syncthreads();
    for (int s = 128; s > 0; s >>= 1) { if (tid < s) red[tid] += red[tid + s]; __syncthreads(); }
    if (tid == 0) { g_lm[row * 4 + qtr] = mx; g_ls[row * 4 + qtr] = red[0]; }
}

// ---------------- kernel 4b: merge quarters + dots + 3 CE terms (256 blocks) ----------------
__global__ __launch_bounds__(256) void k_ce(const float* __restrict__ f,
                                            const float* __restrict__ f_nv,
                                            const float* __restrict__ feat,
                                            const int* __restrict__ indexes) {
    __shared__ float red[256];
    __shared__ float sM, sS;
    const int row = blockIdx.x;
    const int tid = threadIdx.x;

    if (tid == 0) {
        float M = -1e30f;
        #pragma unroll
        for (int i = 0; i < 4; i++) M = fmaxf(M, g_lm[row * 4 + i]);
        float S = 0.f;
        #pragma unroll
        for (int i = 0; i < 4; i++) S += g_ls[row * 4 + i] * expf((g_lm[row * 4 + i] - M) / 0.07f);
        sM = M; sS = S;
    }

    // dots: positives_wogan = f[row] . feat[idx1];  l_pos = f_nv[row] . feat[indexes[row]]
    const int idx1 = g_posidx1[row];
    const int bidx = indexes[row];
    const float* frow = f + (size_t)row * DIM;
    const float* fvrow = f_nv + (size_t)row * DIM;
    const float* k1r = feat + (size_t)idx1 * DIM;
    const float* kbr = feat + (size_t)bidx * DIM;
    float d1 = 0.f, d2 = 0.f;
    for (int d = tid; d < DIM; d += 256) { d1 += frow[d] * k1r[d]; d2 += fvrow[d] * kbr[d]; }
    red[tid] = d1; __syncthreads();
    for (int s = 128; s > 0; s >>= 1) { if (tid < s) red[tid] += red[tid + s]; __syncthreads(); }
    d1 = red[0]; __syncthreads();
    red[tid] = d2; __syncthreads();
    for (int s = 128; s > 0; s >>= 1) { if (tid < s) red[tid] += red[tid + s]; __syncthreads(); }
    d2 = red[0]; __syncthreads();

    if (tid == 0) {
        const float* simr = g_sim + (size_t)row * NBANK;
        float p2 = simr[g_posidx2[row]];
        float c = sM / 0.07f;
        float sum = sS;
        float ce = 0.f;
        float ps[3] = {d2, p2, d1};   // self (l_pos), inter (g2->mat_sim), wogan (g1->mat)
        #pragma unroll
        for (int q = 0; q < 3; q++) {
            float a = ps[q] / 0.07f;
            float M2 = fmaxf(a, c);
            float l = M2 + logf(expf(a - M2) + sum * expf(c - M2));
            ce += l - a;
        }
        g_ce[row] = ce;
    }
}

__global__ void k_final(float* lossOut) {
    __shared__ float red[256];
    int t = threadIdx.x;
    red[t] = g_ce[t]; __syncthreads();
    for (int s = 128; s > 0; s >>= 1) { if (t < s) red[t] += red[t + s]; __syncthreads(); }
    if (t == 0 && lossOut) *lossOut = red[0] / 256.f;
}

// ---------------- kernel 5: momentum update of the 256 touched rows (last-occurrence wins) ----------------
__global__ __launch_bounds__(256) void k_update(const float* __restrict__ f,
                                                const float* __restrict__ feat,
                                                const int* __restrict__ indexes,
                                                float* __restrict__ featOut) {
    const int b = blockIdx.x;
    const int t = threadIdx.x;
    const int idx = indexes[b];
    for (int b2 = b + 1; b2 < BATCH; b2++)
        if (indexes[b2] == idx) return;   // a later write wins; skip (uniform across block)

    __shared__ float red[256];
    const float* kr = feat + (size_t)idx * DIM;
    const float* fr = f + (size_t)b * DIM;
    float u[8]; float ss = 0.f;
    #pragma unroll
    for (int i = 0; i < 8; i++) {
        int d = t + i * 256;
        float v = 0.2f * kr[d] + 0.8f * fr[d];
        u[i] = v; ss += v * v;
    }
    red[t] = ss; __syncthreads();
    for (int s = 128; s > 0; s >>= 1) { if (t < s) red[t] += red[t + s]; __syncthreads(); }
    float den = fmaxf(sqrtf(red[0]), 1e-12f);
    #pragma unroll
    for (int i = 0; i < 8; i++) featOut[(size_t)idx * DIM + t + i * 256] = u[i] / den;
}

// ---------------- launcher ----------------
// Stream/events are created ONCE on the first (uncaptured correctness) call and
// reused thereafter; every call performs identical work on identical inputs.
// Graph fork/join: s2 = {copy -> select}, main = {gemm}; join before k_lse
// (needs select's bitmap + gemm's sim) and before k_update (needs copy).
extern "C" void kernel_launch(void* const* d_in, const int* in_sizes, int n_in,
                              void* d_out, int out_size) {
    const float* f      = (const float*)d_in[0];
    const float* f_nv   = (const float*)d_in[1];
    const float* feat   = (const float*)d_in[2];
    const int*   labels = (const int*)d_in[3];
    const int*   indexes= (const int*)d_in[4];
    (void)in_sizes; (void)n_in;

    float* out = (float*)d_out;
    float* lossOut = out;
    float* featOut = out + 1;                 // pytree order: (loss, new_features)
    const long long nd = (long long)NBANK * DIM;
    if ((long long)out_size == nd) { featOut = out; lossOut = nullptr; }
    else if (out_size == 1)        { featOut = nullptr; }

    static cudaStream_t s2 = nullptr;
    static cudaEvent_t evFork = nullptr, evJoin = nullptr, evSel = nullptr;
    if (!s2) {
        cudaStreamCreateWithFlags(&s2, cudaStreamNonBlocking);
        cudaEventCreateWithFlags(&evFork, cudaEventDisableTiming);
        cudaEventCreateWithFlags(&evJoin, cudaEventDisableTiming);
        cudaEventCreateWithFlags(&evSel, cudaEventDisableTiming);
    }

    const int smemSel = (NBANK + 2048 + 4096 + 1024 + 512) * 4;  // 161792 B
    cudaFuncSetAttribute(k_select, cudaFuncAttributeMaxDynamicSharedMemorySize, smemSel);
    const int smemGemm = 4 * GSTG * (int)sizeof(float);          // 73728 B
    cudaFuncSetAttribute(k_gemm, cudaFuncAttributeMaxDynamicSharedMemorySize, smemGemm);

    // fork: s2 runs {copy (if needed) -> select}, overlapped with gemm on main
    cudaEventRecord(evFork, 0);
    cudaStreamWaitEvent(s2, evFork, 0);
    if (featOut) {
        int p = (int)((4 - ((((uintptr_t)featOut) >> 2) & 3)) & 3);  // floats to 16B alignment
        k_copy_shift<<<8192, 256, 0, s2>>>(feat, featOut, p);
        cudaEventRecord(evJoin, s2);
    }
    k_select<<<BATCH, 512, smemSel, s2>>>(labels, indexes);
    cudaEventRecord(evSel, s2);

    dim3 gg(BATCH / 128, NBANK / 128);        // (mTiles=2, nTiles=256): B-tile L2 reuse
    k_gemm<<<gg, 256, smemGemm>>>(f_nv, feat);

    cudaStreamWaitEvent(0, evSel, 0);         // join: select results needed below
    k_lse<<<BATCH * 4, 256>>>();
    k_ce<<<BATCH, 256>>>(f, f_nv, feat, indexes);
    if (lossOut) k_final<<<1, 256>>>(lossOut);

    if (featOut) {
        cudaStreamWaitEvent(0, evJoin, 0);    // join: copy must land before row updates
        k_update<<<BATCH, 256>>>(f, feat, indexes, featOut);
    }
}